// round 15
// baseline (speedup 1.0000x reference)
#include <cuda_runtime.h>
#include <cuda_fp16.h>
#include <math_constants.h>

#define NN 50000
#define NE 800000
#define FIN 128
#define DD 64
#define HH 4
#define HD 256   // H*D
#define EDIM 20

#define SCHUNK 200
#define NSB 250   // NSB * SCHUNK == NN

// ---------------- scratch (device globals) ----------------
__device__ __half g_hh[NN * DD];         // 6.4 MB node features (fp16)
__device__ __half g_xl[NN * HD];         // 25.6 MB (fp16)
__device__ __half g_xr[NN * HD];         // 25.6 MB (fp16)
__device__ float  g_score[NE * HH];      // 12.8 MB per-edge per-head scores
__device__ float  g_smax[NN * HH];       // per-node per-head score max
__device__ __half g_Wt[512 * 64];        // [n][k] fp16: n<256 -> Wl, else Wr
__device__ __half g_Wep[256 * 32];       // [n][k] fp16: We^T zero-padded K 20->32
__device__ int    g_cnt[NN];
__device__ int    g_cur[NN];
__device__ int    g_rowptr[NN + 1];
__device__ int    g_bsum[NSB];
__device__ int    g_csr_src[NE];
__device__ int    g_csr_dst[NE];
__device__ int    g_csr_eid[NE];

__device__ __forceinline__ void atomicMaxF(float* addr, float v) {
    // valid with init = -inf
    if (v >= 0.f) atomicMax((int*)addr, __float_as_int(v));
    else          atomicMin((unsigned int*)addr, __float_as_uint(v));
}

// ------- h0 = relu(x @ f_W + f_b) (fp16) + zero cnt/cur + weight converts ---
__global__ void k_h0(const float* __restrict__ x, const float* __restrict__ fW,
                     const float* __restrict__ fb, const float* __restrict__ Wl,
                     const float* __restrict__ Wr, const float* __restrict__ We) {
    __shared__ float Ws[FIN * DD];
    __shared__ float xs[16][FIN];
    int t = threadIdx.x;
    int gi = blockIdx.x * 256 + t;
    if (gi < NN) { g_cnt[gi] = 0; g_cur[gi] = 0; }
    if (gi < 512 * 64) {
        int nn = gi >> 6, k = gi & 63;
        const float* W = (nn < 256) ? Wl : Wr;
        g_Wt[gi] = __float2half(W[k * HD + (nn & 255)]);
    }
    {
        int j = gi - 512 * 64;
        if (j >= 0 && j < 256 * 32) {
            int nn = j >> 5, k = j & 31;
            g_Wep[j] = (k < EDIM) ? __float2half(We[k * HD + nn]) : __half(0);
        }
    }
    for (int i = t; i < FIN * DD; i += 256) Ws[i] = fW[i];
    int n0 = blockIdx.x * 16;
    for (int i = t; i < 16 * FIN; i += 256) {
        int r = i / FIN, k = i % FIN;
        int n = n0 + r;
        xs[r][k] = (n < NN) ? x[n * FIN + k] : 0.f;
    }
    __syncthreads();
    int rg = t >> 6, d = t & 63;
    float b = fb[d];
    float acc[4] = {b, b, b, b};
#pragma unroll 8
    for (int k = 0; k < FIN; k++) {
        float w = Ws[k * DD + d];
#pragma unroll
        for (int q = 0; q < 4; q++) acc[q] = fmaf(xs[rg * 4 + q][k], w, acc[q]);
    }
#pragma unroll
    for (int q = 0; q < 4; q++) {
        int n = n0 + rg * 4 + q;
        if (n < NN) g_hh[n * DD + d] = __float2half(fmaxf(acc[q], 0.f));
    }
}

// ---------------- CSR build ----------------
__global__ void k_hist(const int* __restrict__ ei) {
    int e = blockIdx.x * blockDim.x + threadIdx.x;
    if (e < NE) atomicAdd(&g_cnt[ei[NE + e]], 1);
}

__global__ void k_scan_a() {
    __shared__ int s[256];
    int b = blockIdx.x, t = threadIdx.x;
    s[t] = (t < SCHUNK) ? g_cnt[b * SCHUNK + t] : 0;
    __syncthreads();
    for (int off = 128; off; off >>= 1) {
        if (t < off) s[t] += s[t + off];
        __syncthreads();
    }
    if (t == 0) g_bsum[b] = s[0];
}

__global__ void k_scan_bc() {
    __shared__ int sb[256];
    __shared__ int s[256];
    __shared__ int cnt_s[256];
    int b = blockIdx.x, t = threadIdx.x;
    sb[t] = (t < NSB) ? g_bsum[t] : 0;
    int c = (t < SCHUNK) ? g_cnt[b * SCHUNK + t] : 0;
    cnt_s[t] = c;
    s[t] = c;
    __syncthreads();
    for (int off = 1; off < 256; off <<= 1) {
        int v1 = (t >= off) ? sb[t - off] : 0;
        int v2 = (t >= off) ? s[t - off] : 0;
        __syncthreads();
        sb[t] += v1;
        s[t] += v2;
        __syncthreads();
    }
    if (t < SCHUNK) {
        int base = (b > 0) ? sb[b - 1] : 0;
        g_rowptr[b * SCHUNK + t] = base + s[t] - cnt_s[t];  // exclusive
    }
    if (b == 0 && t == 0) g_rowptr[NN] = NE;
}

__global__ void k_scatter(const int* __restrict__ ei) {
    int e = blockIdx.x * blockDim.x + threadIdx.x;
    if (e >= NE) return;
    int dst = ei[NE + e];
    int pos = g_rowptr[dst] + atomicAdd(&g_cur[dst], 1);
    g_csr_src[pos] = ei[e];
    g_csr_dst[pos] = dst;
    g_csr_eid[pos] = e;
}

// ---------------- per-layer: g_smax = -inf ----------------
__global__ void k_init_smax() {
    int i = blockIdx.x * blockDim.x + threadIdx.x;
    if (i < NN * HH) g_smax[i] = __int_as_float(0xff800000u);
}

// ---------------- xl/xr = hh @ [Wl|Wr] + bias (tensor cores, fp16 out) -----
__global__ void __launch_bounds__(256) k_lin_tc(const float* __restrict__ bl,
                                                const float* __restrict__ br) {
    __shared__ __half As[128][72];
    __shared__ __half Bs[64][72];
    int t = threadIdx.x;
    int warp = t >> 5, lane = t & 31;
    int m0 = blockIdx.x * 128;
    int n0 = blockIdx.y * 64;

    for (int i = t; i < 128 * 8; i += 256) {
        int r = i >> 3, c = i & 7;
        uint4 v = make_uint4(0, 0, 0, 0);
        if (m0 + r < NN) v = ((const uint4*)(g_hh + (size_t)(m0 + r) * DD))[c];
        *(uint4*)&As[r][c * 8] = v;
    }
    for (int i = t; i < 64 * 8; i += 256) {
        int r = i >> 3, c = i & 7;
        *(uint4*)&Bs[r][c * 8] = ((const uint4*)(g_Wt + (size_t)(n0 + r) * 64))[c];
    }
    __syncthreads();

    float acc[8][4];
#pragma unroll
    for (int j = 0; j < 8; j++)
#pragma unroll
        for (int q = 0; q < 4; q++) acc[j][q] = 0.f;

#pragma unroll
    for (int k0 = 0; k0 < 64; k0 += 16) {
        unsigned a0, a1, a2, a3;
        {
            int ar = warp * 16 + (lane & 15);
            int ac = k0 + ((lane >> 4) << 3);
            unsigned aaddr = (unsigned)__cvta_generic_to_shared(&As[ar][ac]);
            asm volatile("ldmatrix.sync.aligned.m8n8.x4.shared.b16 {%0,%1,%2,%3}, [%4];"
                         : "=r"(a0), "=r"(a1), "=r"(a2), "=r"(a3) : "r"(aaddr));
        }
#pragma unroll
        for (int j = 0; j < 8; j++) {
            unsigned b0, b1;
            {
                int brow = j * 8 + (lane & 7);
                int bcol = k0 + (((lane >> 3) & 1) << 3);
                unsigned baddr = (unsigned)__cvta_generic_to_shared(&Bs[brow][bcol]);
                asm volatile("ldmatrix.sync.aligned.m8n8.x2.shared.b16 {%0,%1}, [%2];"
                             : "=r"(b0), "=r"(b1) : "r"(baddr));
            }
            asm volatile(
                "mma.sync.aligned.m16n8k16.row.col.f32.f16.f16.f32 "
                "{%0,%1,%2,%3}, {%4,%5,%6,%7}, {%8,%9}, {%0,%1,%2,%3};"
                : "+f"(acc[j][0]), "+f"(acc[j][1]), "+f"(acc[j][2]), "+f"(acc[j][3])
                : "r"(a0), "r"(a1), "r"(a2), "r"(a3), "r"(b0), "r"(b1));
        }
    }

    int row_base = m0 + warp * 16 + (lane >> 2);
    int isL = (n0 < HD);
    const float* bb = isL ? bl : br;
    __half* dst = isL ? g_xl : g_xr;
    int cb = n0 & (HD - 1);
#pragma unroll
    for (int j = 0; j < 8; j++) {
        int col = cb + j * 8 + (lane & 3) * 2;
        float bv0 = __ldg(&bb[col]), bv1 = __ldg(&bb[col + 1]);
#pragma unroll
        for (int half = 0; half < 2; half++) {
            int row = row_base + half * 8;
            if (row >= NN) continue;
            float v0 = acc[j][half * 2 + 0] + bv0;
            float v1 = acc[j][half * 2 + 1] + bv1;
            *(__half2*)(dst + (size_t)row * HD + col) = __floats2half2_rn(v0, v1);
        }
    }
}

// ---------------- per-layer edge scores (tensor-core ee recompute) ---------
// grid NE/128; block 256 (8 warps). Per block: 128 CSR-ordered edges.
// Also folds the segment-max into g_smax via atomic RED.
__global__ void __launch_bounds__(256) k_score_tc(const float* __restrict__ ea,
                                                  const float* __restrict__ feW,
                                                  const float* __restrict__ feb,
                                                  const float* __restrict__ att) {
    __shared__ float  eas[128][2];
    __shared__ __half As[128][40];
    __shared__ __half Bs[64][40];
    __shared__ __half Zs[128][72];
    __shared__ float  satt[64];
    __shared__ float  sacc[128][4];
    __shared__ int    ssrc[128], sdst[128];
    int t = threadIdx.x;
    int warp = t >> 5, lane = t & 31;
    int e0 = blockIdx.x * 128;

    if (t < 128) {
        int eid = g_csr_eid[e0 + t];
        float2 a = __ldg(&((const float2*)ea)[eid]);
        eas[t][0] = a.x; eas[t][1] = a.y;
        ssrc[t] = g_csr_src[e0 + t];
        sdst[t] = g_csr_dst[e0 + t];
    }
    __syncthreads();
    for (int i = t; i < 128 * 32; i += 256) {
        int r = i >> 5, k = i & 31;
        __half v = __half(0);
        if (k < EDIM) {
            float f = fmaf(eas[r][0], __ldg(&feW[k]),
                      fmaf(eas[r][1], __ldg(&feW[EDIM + k]), __ldg(&feb[k])));
            v = __float2half(fmaxf(f, 0.f));
        }
        As[r][k] = v;
    }
    __syncthreads();

    for (int chunk = 0; chunk < 4; chunk++) {
        int n0 = chunk * 64;
        for (int i = t; i < 64 * 4; i += 256) {
            int r = i >> 2, c = i & 3;
            *(uint4*)&Bs[r][c * 8] = ((const uint4*)(g_Wep + (size_t)(n0 + r) * 32))[c];
        }
        if (t < 64) satt[t] = __ldg(&att[n0 + t]);
        for (int i = t; i < 128 * 8; i += 256) {
            int r = i >> 3, c = i & 7;
            uint4 a = ((const uint4*)(g_xl + (size_t)ssrc[r] * HD + n0))[c];
            uint4 b = ((const uint4*)(g_xr + (size_t)sdst[r] * HD + n0))[c];
            uint4 z;
            *(__half2*)&z.x = __hadd2(*(__half2*)&a.x, *(__half2*)&b.x);
            *(__half2*)&z.y = __hadd2(*(__half2*)&a.y, *(__half2*)&b.y);
            *(__half2*)&z.z = __hadd2(*(__half2*)&a.z, *(__half2*)&b.z);
            *(__half2*)&z.w = __hadd2(*(__half2*)&a.w, *(__half2*)&b.w);
            *(uint4*)&Zs[r][c * 8] = z;
        }
        __syncthreads();

        float acc[8][4];
#pragma unroll
        for (int j = 0; j < 8; j++)
#pragma unroll
            for (int q = 0; q < 4; q++) acc[j][q] = 0.f;

#pragma unroll
        for (int k0 = 0; k0 < 32; k0 += 16) {
            unsigned a0, a1, a2, a3;
            {
                int ar = warp * 16 + (lane & 15);
                int ac = k0 + ((lane >> 4) << 3);
                unsigned aaddr = (unsigned)__cvta_generic_to_shared(&As[ar][ac]);
                asm volatile("ldmatrix.sync.aligned.m8n8.x4.shared.b16 {%0,%1,%2,%3}, [%4];"
                             : "=r"(a0), "=r"(a1), "=r"(a2), "=r"(a3) : "r"(aaddr));
            }
#pragma unroll
            for (int j = 0; j < 8; j++) {
                unsigned b0, b1;
                {
                    int brow = j * 8 + (lane & 7);
                    int bcol = k0 + (((lane >> 3) & 1) << 3);
                    unsigned baddr = (unsigned)__cvta_generic_to_shared(&Bs[brow][bcol]);
                    asm volatile("ldmatrix.sync.aligned.m8n8.x2.shared.b16 {%0,%1}, [%2];"
                                 : "=r"(b0), "=r"(b1) : "r"(baddr));
                }
                asm volatile(
                    "mma.sync.aligned.m16n8k16.row.col.f32.f16.f16.f32 "
                    "{%0,%1,%2,%3}, {%4,%5,%6,%7}, {%8,%9}, {%0,%1,%2,%3};"
                    : "+f"(acc[j][0]), "+f"(acc[j][1]), "+f"(acc[j][2]), "+f"(acc[j][3])
                    : "r"(a0), "r"(a1), "r"(a2), "r"(a3), "r"(b0), "r"(b1));
            }
        }

        int row0 = warp * 16 + (lane >> 2);
        float s0 = 0.f, s1 = 0.f;
#pragma unroll
        for (int j = 0; j < 8; j++) {
            int col = j * 8 + (lane & 3) * 2;
            float a0 = satt[col], a1 = satt[col + 1];
            float2 z0 = __half22float2(*(__half2*)&Zs[row0][col]);
            float2 z1 = __half22float2(*(__half2*)&Zs[row0 + 8][col]);
            float m;
            m = acc[j][0] + z0.x; m = m > 0.f ? m : 0.2f * m; s0 = fmaf(a0, m, s0);
            m = acc[j][1] + z0.y; m = m > 0.f ? m : 0.2f * m; s0 = fmaf(a1, m, s0);
            m = acc[j][2] + z1.x; m = m > 0.f ? m : 0.2f * m; s1 = fmaf(a0, m, s1);
            m = acc[j][3] + z1.y; m = m > 0.f ? m : 0.2f * m; s1 = fmaf(a1, m, s1);
        }
        s0 += __shfl_xor_sync(0xffffffffu, s0, 1);
        s0 += __shfl_xor_sync(0xffffffffu, s0, 2);
        s1 += __shfl_xor_sync(0xffffffffu, s1, 1);
        s1 += __shfl_xor_sync(0xffffffffu, s1, 2);
        if ((lane & 3) == 0) {
            sacc[row0][chunk]     = s0;
            sacc[row0 + 8][chunk] = s1;
        }
        __syncthreads();
    }
    if (t < 128) {
        float4 sv = *(float4*)&sacc[t][0];
        ((float4*)g_score)[e0 + t] = sv;
        int dst = sdst[t];
        atomicMaxF(&g_smax[dst * 4 + 0], sv.x);
        atomicMaxF(&g_smax[dst * 4 + 1], sv.y);
        atomicMaxF(&g_smax[dst * 4 + 2], sv.z);
        atomicMaxF(&g_smax[dst * 4 + 3], sv.w);
    }
}

// ---------------- aggregation: exp/accumulate (max precomputed) + mean ------
__global__ void __launch_bounds__(256) k_agg(const float* __restrict__ bias,
                                             float* __restrict__ dout, int writeOut) {
    int t = threadIdx.x;
    int wid = t >> 5, lane = t & 31;
    int n = blockIdx.x * 8 + wid;
    if (n >= NN) return;

    int beg = g_rowptr[n], end = g_rowptr[n + 1];
    int h = lane >> 3;

    float mx = __ldg(&g_smax[n * 4 + h]);

    float den = 0.f;
    float acc[8];
#pragma unroll
    for (int k = 0; k < 8; k++) acc[k] = 0.f;

#define PROCESS(XU, SV)                                                       \
    {                                                                         \
        float w = __expf((SV) - mx);                                          \
        den += w;                                                             \
        float2 x0 = __half22float2(*(__half2*)&(XU).x);                       \
        float2 x1 = __half22float2(*(__half2*)&(XU).y);                       \
        float2 x2 = __half22float2(*(__half2*)&(XU).z);                       \
        float2 x3 = __half22float2(*(__half2*)&(XU).w);                       \
        acc[0] = fmaf(w, x0.x, acc[0]); acc[1] = fmaf(w, x0.y, acc[1]);       \
        acc[2] = fmaf(w, x1.x, acc[2]); acc[3] = fmaf(w, x1.y, acc[3]);       \
        acc[4] = fmaf(w, x2.x, acc[4]); acc[5] = fmaf(w, x2.y, acc[5]);       \
        acc[6] = fmaf(w, x3.x, acc[6]); acc[7] = fmaf(w, x3.y, acc[7]);       \
    }

#define LOADP(XX, SS, p)                                                      \
    {                                                                         \
        int _src = __ldg(&g_csr_src[(p)]);                                    \
        XX = __ldg(&((const uint4*)(g_xl + (size_t)_src * HD))[lane]);        \
        SS = __ldg(&g_score[(p) * 4 + h]);                                    \
    }

    {
        uint4 X0, X1; float S0 = 0.f, S1 = 0.f;
        if (beg < end)     LOADP(X0, S0, beg);
        if (beg + 1 < end) LOADP(X1, S1, beg + 1);
        for (int p = beg; p < end; p += 2) {
            PROCESS(X0, S0);
            if (p + 2 < end) LOADP(X0, S0, p + 2);
            if (p + 1 < end) {
                PROCESS(X1, S1);
                if (p + 3 < end) LOADP(X1, S1, p + 3);
            }
        }
    }
#undef LOADP
#undef PROCESS

    float inv = (end > beg) ? 1.f / den : 0.f;
    float v[8];
#pragma unroll
    for (int k = 0; k < 8; k++) v[k] = acc[k] * inv;
#pragma unroll
    for (int k = 0; k < 8; k++) {
        v[k] += __shfl_xor_sync(0xffffffffu, v[k], 8);
        v[k] += __shfl_xor_sync(0xffffffffu, v[k], 16);
    }
    if (lane < 8) {
        float4 b0 = __ldg(&((const float4*)bias)[lane * 2]);
        float4 b1 = __ldg(&((const float4*)bias)[lane * 2 + 1]);
        float o[8];
        o[0] = fmaxf(0.25f * v[0] + b0.x, 0.f);
        o[1] = fmaxf(0.25f * v[1] + b0.y, 0.f);
        o[2] = fmaxf(0.25f * v[2] + b0.z, 0.f);
        o[3] = fmaxf(0.25f * v[3] + b0.w, 0.f);
        o[4] = fmaxf(0.25f * v[4] + b1.x, 0.f);
        o[5] = fmaxf(0.25f * v[5] + b1.y, 0.f);
        o[6] = fmaxf(0.25f * v[6] + b1.z, 0.f);
        o[7] = fmaxf(0.25f * v[7] + b1.w, 0.f);
        if (writeOut) {
            ((float4*)(dout + n * DD))[lane * 2]     = make_float4(o[0], o[1], o[2], o[3]);
            ((float4*)(dout + n * DD))[lane * 2 + 1] = make_float4(o[4], o[5], o[6], o[7]);
        } else {
            __half2 h0 = __floats2half2_rn(o[0], o[1]);
            __half2 h1 = __floats2half2_rn(o[2], o[3]);
            __half2 h2 = __floats2half2_rn(o[4], o[5]);
            __half2 h3 = __floats2half2_rn(o[6], o[7]);
            uint4 u;
            u.x = *(unsigned int*)&h0; u.y = *(unsigned int*)&h1;
            u.z = *(unsigned int*)&h2; u.w = *(unsigned int*)&h3;
            ((uint4*)(g_hh + (size_t)n * DD))[lane] = u;
        }
    }
}

// ---------------- launch ----------------
extern "C" void kernel_launch(void* const* d_in, const int* in_sizes, int n_in,
                              void* d_out, int out_size) {
    const float* x   = (const float*)d_in[0];
    const float* ea  = (const float*)d_in[1];
    const int*   ei  = (const int*)  d_in[2];
    const float* fW  = (const float*)d_in[3];
    const float* fb  = (const float*)d_in[4];
    const float* feW = (const float*)d_in[5];
    const float* feb = (const float*)d_in[6];
    const float* Wl  = (const float*)d_in[7];
    const float* bl  = (const float*)d_in[8];
    const float* Wr  = (const float*)d_in[9];
    const float* br  = (const float*)d_in[10];
    const float* We  = (const float*)d_in[11];
    const float* att = (const float*)d_in[12];
    const float* bias= (const float*)d_in[13];

    // prologue
    k_h0<<<(NN + 15) / 16, 256>>>(x, fW, fb, Wl, Wr, We);
    k_hist<<<(NE + 255) / 256, 256>>>(ei);
    k_scan_a<<<NSB, 256>>>();
    k_scan_bc<<<NSB, 256>>>();
    k_scatter<<<(NE + 255) / 256, 256>>>(ei);

    for (int l = 0; l < 3; l++) {
        k_lin_tc<<<dim3((NN + 127) / 128, 8), 256>>>(bl, br);
        k_init_smax<<<(NN * HH + 255) / 256, 256>>>();
        k_score_tc<<<NE / 128, 256>>>(ea, feW, feb, att);
        k_agg<<<(NN + 7) / 8, 256>>>(bias, (float*)d_out, l == 2 ? 1 : 0);
    }
}

// round 16
// speedup vs baseline: 1.0742x; 1.0742x over previous
#include <cuda_runtime.h>
#include <cuda_fp16.h>
#include <math_constants.h>

#define NN 50000
#define NE 800000
#define FIN 128
#define DD 64
#define HH 4
#define HD 256   // H*D
#define EDIM 20

#define SCHUNK 200
#define NSB 250   // NSB * SCHUNK == NN

// ---------------- scratch (device globals) ----------------
__device__ __half g_hh[NN * DD];         // 6.4 MB node features (fp16)
__device__ __half g_xl[NN * HD];         // 25.6 MB (fp16)
__device__ __half g_xr[NN * HD];         // 25.6 MB (fp16)
__device__ float  g_score[NE * HH];      // 12.8 MB per-edge per-head exp(score)
__device__ __half g_Wt[512 * 64];        // [n][k] fp16: n<256 -> Wl, else Wr
__device__ __half g_Wep[256 * 32];       // [n][k] fp16: We^T zero-padded K 20->32
__device__ int    g_cnt[NN];
__device__ int    g_cur[NN];
__device__ int    g_rowptr[NN + 1];
__device__ int    g_bsum[NSB];
__device__ int    g_csr_src[NE];
__device__ int    g_csr_dst[NE];
__device__ int    g_csr_eid[NE];

// ------- h0 = relu(x @ f_W + f_b) (fp16) + zero cnt/cur + weight converts ---
__global__ void k_h0(const float* __restrict__ x, const float* __restrict__ fW,
                     const float* __restrict__ fb, const float* __restrict__ Wl,
                     const float* __restrict__ Wr, const float* __restrict__ We) {
    __shared__ float Ws[FIN * DD];
    __shared__ float xs[16][FIN];
    int t = threadIdx.x;
    int gi = blockIdx.x * 256 + t;
    if (gi < NN) { g_cnt[gi] = 0; g_cur[gi] = 0; }
    if (gi < 512 * 64) {
        int nn = gi >> 6, k = gi & 63;
        const float* W = (nn < 256) ? Wl : Wr;
        g_Wt[gi] = __float2half(W[k * HD + (nn & 255)]);
    }
    {
        int j = gi - 512 * 64;
        if (j >= 0 && j < 256 * 32) {
            int nn = j >> 5, k = j & 31;
            g_Wep[j] = (k < EDIM) ? __float2half(We[k * HD + nn]) : __half(0);
        }
    }
    for (int i = t; i < FIN * DD; i += 256) Ws[i] = fW[i];
    int n0 = blockIdx.x * 16;
    for (int i = t; i < 16 * FIN; i += 256) {
        int r = i / FIN, k = i % FIN;
        int n = n0 + r;
        xs[r][k] = (n < NN) ? x[n * FIN + k] : 0.f;
    }
    __syncthreads();
    int rg = t >> 6, d = t & 63;
    float b = fb[d];
    float acc[4] = {b, b, b, b};
#pragma unroll 8
    for (int k = 0; k < FIN; k++) {
        float w = Ws[k * DD + d];
#pragma unroll
        for (int q = 0; q < 4; q++) acc[q] = fmaf(xs[rg * 4 + q][k], w, acc[q]);
    }
#pragma unroll
    for (int q = 0; q < 4; q++) {
        int n = n0 + rg * 4 + q;
        if (n < NN) g_hh[n * DD + d] = __float2half(fmaxf(acc[q], 0.f));
    }
}

// ---------------- CSR build ----------------
__global__ void k_hist(const int* __restrict__ ei) {
    int e = blockIdx.x * blockDim.x + threadIdx.x;
    if (e < NE) atomicAdd(&g_cnt[ei[NE + e]], 1);
}

__global__ void k_scan_a() {
    __shared__ int s[256];
    int b = blockIdx.x, t = threadIdx.x;
    s[t] = (t < SCHUNK) ? g_cnt[b * SCHUNK + t] : 0;
    __syncthreads();
    for (int off = 128; off; off >>= 1) {
        if (t < off) s[t] += s[t + off];
        __syncthreads();
    }
    if (t == 0) g_bsum[b] = s[0];
}

__global__ void k_scan_bc() {
    __shared__ int sb[256];
    __shared__ int s[256];
    __shared__ int cnt_s[256];
    int b = blockIdx.x, t = threadIdx.x;
    sb[t] = (t < NSB) ? g_bsum[t] : 0;
    int c = (t < SCHUNK) ? g_cnt[b * SCHUNK + t] : 0;
    cnt_s[t] = c;
    s[t] = c;
    __syncthreads();
    for (int off = 1; off < 256; off <<= 1) {
        int v1 = (t >= off) ? sb[t - off] : 0;
        int v2 = (t >= off) ? s[t - off] : 0;
        __syncthreads();
        sb[t] += v1;
        s[t] += v2;
        __syncthreads();
    }
    if (t < SCHUNK) {
        int base = (b > 0) ? sb[b - 1] : 0;
        g_rowptr[b * SCHUNK + t] = base + s[t] - cnt_s[t];  // exclusive
    }
    if (b == 0 && t == 0) g_rowptr[NN] = NE;
}

__global__ void k_scatter(const int* __restrict__ ei) {
    int e = blockIdx.x * blockDim.x + threadIdx.x;
    if (e >= NE) return;
    int dst = ei[NE + e];
    int pos = g_rowptr[dst] + atomicAdd(&g_cur[dst], 1);
    g_csr_src[pos] = ei[e];
    g_csr_dst[pos] = dst;
    g_csr_eid[pos] = e;
}

// ---------------- xl/xr = hh @ [Wl|Wr] + bias (tensor cores, fp16 out) -----
__global__ void __launch_bounds__(256) k_lin_tc(const float* __restrict__ bl,
                                                const float* __restrict__ br) {
    __shared__ __half As[128][72];
    __shared__ __half Bs[64][72];
    int t = threadIdx.x;
    int warp = t >> 5, lane = t & 31;
    int m0 = blockIdx.x * 128;
    int n0 = blockIdx.y * 64;

    for (int i = t; i < 128 * 8; i += 256) {
        int r = i >> 3, c = i & 7;
        uint4 v = make_uint4(0, 0, 0, 0);
        if (m0 + r < NN) v = ((const uint4*)(g_hh + (size_t)(m0 + r) * DD))[c];
        *(uint4*)&As[r][c * 8] = v;
    }
    for (int i = t; i < 64 * 8; i += 256) {
        int r = i >> 3, c = i & 7;
        *(uint4*)&Bs[r][c * 8] = ((const uint4*)(g_Wt + (size_t)(n0 + r) * 64))[c];
    }
    __syncthreads();

    float acc[8][4];
#pragma unroll
    for (int j = 0; j < 8; j++)
#pragma unroll
        for (int q = 0; q < 4; q++) acc[j][q] = 0.f;

#pragma unroll
    for (int k0 = 0; k0 < 64; k0 += 16) {
        unsigned a0, a1, a2, a3;
        {
            int ar = warp * 16 + (lane & 15);
            int ac = k0 + ((lane >> 4) << 3);
            unsigned aaddr = (unsigned)__cvta_generic_to_shared(&As[ar][ac]);
            asm volatile("ldmatrix.sync.aligned.m8n8.x4.shared.b16 {%0,%1,%2,%3}, [%4];"
                         : "=r"(a0), "=r"(a1), "=r"(a2), "=r"(a3) : "r"(aaddr));
        }
#pragma unroll
        for (int j = 0; j < 8; j++) {
            unsigned b0, b1;
            {
                int brow = j * 8 + (lane & 7);
                int bcol = k0 + (((lane >> 3) & 1) << 3);
                unsigned baddr = (unsigned)__cvta_generic_to_shared(&Bs[brow][bcol]);
                asm volatile("ldmatrix.sync.aligned.m8n8.x2.shared.b16 {%0,%1}, [%2];"
                             : "=r"(b0), "=r"(b1) : "r"(baddr));
            }
            asm volatile(
                "mma.sync.aligned.m16n8k16.row.col.f32.f16.f16.f32 "
                "{%0,%1,%2,%3}, {%4,%5,%6,%7}, {%8,%9}, {%0,%1,%2,%3};"
                : "+f"(acc[j][0]), "+f"(acc[j][1]), "+f"(acc[j][2]), "+f"(acc[j][3])
                : "r"(a0), "r"(a1), "r"(a2), "r"(a3), "r"(b0), "r"(b1));
        }
    }

    int row_base = m0 + warp * 16 + (lane >> 2);
    int isL = (n0 < HD);
    const float* bb = isL ? bl : br;
    __half* dst = isL ? g_xl : g_xr;
    int cb = n0 & (HD - 1);
#pragma unroll
    for (int j = 0; j < 8; j++) {
        int col = cb + j * 8 + (lane & 3) * 2;
        float bv0 = __ldg(&bb[col]), bv1 = __ldg(&bb[col + 1]);
#pragma unroll
        for (int half = 0; half < 2; half++) {
            int row = row_base + half * 8;
            if (row >= NN) continue;
            float v0 = acc[j][half * 2 + 0] + bv0;
            float v1 = acc[j][half * 2 + 1] + bv1;
            *(__half2*)(dst + (size_t)row * HD + col) = __floats2half2_rn(v0, v1);
        }
    }
}

// ---------------- per-layer edge scores (tensor-core ee recompute) ---------
// grid NE/128; block 256 (8 warps). Per block: 128 CSR-ordered edges.
// Stores exp(score) directly (scores are O(1); exp is overflow-safe without max).
__global__ void __launch_bounds__(256) k_score_tc(const float* __restrict__ ea,
                                                  const float* __restrict__ feW,
                                                  const float* __restrict__ feb,
                                                  const float* __restrict__ att) {
    __shared__ float  eas[128][2];
    __shared__ __half As[128][40];
    __shared__ __half Bs[64][40];
    __shared__ __half Zs[128][72];
    __shared__ float  satt[64];
    __shared__ float  sacc[128][4];
    __shared__ int    ssrc[128], sdst[128];
    int t = threadIdx.x;
    int warp = t >> 5, lane = t & 31;
    int e0 = blockIdx.x * 128;

    if (t < 128) {
        int eid = g_csr_eid[e0 + t];
        float2 a = __ldg(&((const float2*)ea)[eid]);
        eas[t][0] = a.x; eas[t][1] = a.y;
        ssrc[t] = g_csr_src[e0 + t];
        sdst[t] = g_csr_dst[e0 + t];
    }
    __syncthreads();
    for (int i = t; i < 128 * 32; i += 256) {
        int r = i >> 5, k = i & 31;
        __half v = __half(0);
        if (k < EDIM) {
            float f = fmaf(eas[r][0], __ldg(&feW[k]),
                      fmaf(eas[r][1], __ldg(&feW[EDIM + k]), __ldg(&feb[k])));
            v = __float2half(fmaxf(f, 0.f));
        }
        As[r][k] = v;
    }
    __syncthreads();

    for (int chunk = 0; chunk < 4; chunk++) {
        int n0 = chunk * 64;
        for (int i = t; i < 64 * 4; i += 256) {
            int r = i >> 2, c = i & 3;
            *(uint4*)&Bs[r][c * 8] = ((const uint4*)(g_Wep + (size_t)(n0 + r) * 32))[c];
        }
        if (t < 64) satt[t] = __ldg(&att[n0 + t]);
        for (int i = t; i < 128 * 8; i += 256) {
            int r = i >> 3, c = i & 7;
            uint4 a = ((const uint4*)(g_xl + (size_t)ssrc[r] * HD + n0))[c];
            uint4 b = ((const uint4*)(g_xr + (size_t)sdst[r] * HD + n0))[c];
            uint4 z;
            *(__half2*)&z.x = __hadd2(*(__half2*)&a.x, *(__half2*)&b.x);
            *(__half2*)&z.y = __hadd2(*(__half2*)&a.y, *(__half2*)&b.y);
            *(__half2*)&z.z = __hadd2(*(__half2*)&a.z, *(__half2*)&b.z);
            *(__half2*)&z.w = __hadd2(*(__half2*)&a.w, *(__half2*)&b.w);
            *(uint4*)&Zs[r][c * 8] = z;
        }
        __syncthreads();

        float acc[8][4];
#pragma unroll
        for (int j = 0; j < 8; j++)
#pragma unroll
            for (int q = 0; q < 4; q++) acc[j][q] = 0.f;

#pragma unroll
        for (int k0 = 0; k0 < 32; k0 += 16) {
            unsigned a0, a1, a2, a3;
            {
                int ar = warp * 16 + (lane & 15);
                int ac = k0 + ((lane >> 4) << 3);
                unsigned aaddr = (unsigned)__cvta_generic_to_shared(&As[ar][ac]);
                asm volatile("ldmatrix.sync.aligned.m8n8.x4.shared.b16 {%0,%1,%2,%3}, [%4];"
                             : "=r"(a0), "=r"(a1), "=r"(a2), "=r"(a3) : "r"(aaddr));
            }
#pragma unroll
            for (int j = 0; j < 8; j++) {
                unsigned b0, b1;
                {
                    int brow = j * 8 + (lane & 7);
                    int bcol = k0 + (((lane >> 3) & 1) << 3);
                    unsigned baddr = (unsigned)__cvta_generic_to_shared(&Bs[brow][bcol]);
                    asm volatile("ldmatrix.sync.aligned.m8n8.x2.shared.b16 {%0,%1}, [%2];"
                                 : "=r"(b0), "=r"(b1) : "r"(baddr));
                }
                asm volatile(
                    "mma.sync.aligned.m16n8k16.row.col.f32.f16.f16.f32 "
                    "{%0,%1,%2,%3}, {%4,%5,%6,%7}, {%8,%9}, {%0,%1,%2,%3};"
                    : "+f"(acc[j][0]), "+f"(acc[j][1]), "+f"(acc[j][2]), "+f"(acc[j][3])
                    : "r"(a0), "r"(a1), "r"(a2), "r"(a3), "r"(b0), "r"(b1));
            }
        }

        int row0 = warp * 16 + (lane >> 2);
        float s0 = 0.f, s1 = 0.f;
#pragma unroll
        for (int j = 0; j < 8; j++) {
            int col = j * 8 + (lane & 3) * 2;
            float a0 = satt[col], a1 = satt[col + 1];
            float2 z0 = __half22float2(*(__half2*)&Zs[row0][col]);
            float2 z1 = __half22float2(*(__half2*)&Zs[row0 + 8][col]);
            float m;
            m = acc[j][0] + z0.x; m = m > 0.f ? m : 0.2f * m; s0 = fmaf(a0, m, s0);
            m = acc[j][1] + z0.y; m = m > 0.f ? m : 0.2f * m; s0 = fmaf(a1, m, s0);
            m = acc[j][2] + z1.x; m = m > 0.f ? m : 0.2f * m; s1 = fmaf(a0, m, s1);
            m = acc[j][3] + z1.y; m = m > 0.f ? m : 0.2f * m; s1 = fmaf(a1, m, s1);
        }
        s0 += __shfl_xor_sync(0xffffffffu, s0, 1);
        s0 += __shfl_xor_sync(0xffffffffu, s0, 2);
        s1 += __shfl_xor_sync(0xffffffffu, s1, 1);
        s1 += __shfl_xor_sync(0xffffffffu, s1, 2);
        if ((lane & 3) == 0) {
            sacc[row0][chunk]     = s0;
            sacc[row0 + 8][chunk] = s1;
        }
        __syncthreads();
    }
    if (t < 128) {
        float4 sv = *(float4*)&sacc[t][0];
        sv.x = __expf(sv.x);
        sv.y = __expf(sv.y);
        sv.z = __expf(sv.z);
        sv.w = __expf(sv.w);
        ((float4*)g_score)[e0 + t] = sv;
    }
}

// ---------------- aggregation: weighted gather (weights pre-exp'd) ---------
__global__ void __launch_bounds__(256) k_agg(const float* __restrict__ bias,
                                             float* __restrict__ dout, int writeOut) {
    int t = threadIdx.x;
    int wid = t >> 5, lane = t & 31;
    int n = blockIdx.x * 8 + wid;
    if (n >= NN) return;

    int beg = g_rowptr[n], end = g_rowptr[n + 1];
    int h = lane >> 3;

    float den = 0.f;
    float acc[8];
#pragma unroll
    for (int k = 0; k < 8; k++) acc[k] = 0.f;

#define PROCESS(XU, SV)                                                       \
    {                                                                         \
        float w = (SV);                                                       \
        den += w;                                                             \
        float2 x0 = __half22float2(*(__half2*)&(XU).x);                       \
        float2 x1 = __half22float2(*(__half2*)&(XU).y);                       \
        float2 x2 = __half22float2(*(__half2*)&(XU).z);                       \
        float2 x3 = __half22float2(*(__half2*)&(XU).w);                       \
        acc[0] = fmaf(w, x0.x, acc[0]); acc[1] = fmaf(w, x0.y, acc[1]);       \
        acc[2] = fmaf(w, x1.x, acc[2]); acc[3] = fmaf(w, x1.y, acc[3]);       \
        acc[4] = fmaf(w, x2.x, acc[4]); acc[5] = fmaf(w, x2.y, acc[5]);       \
        acc[6] = fmaf(w, x3.x, acc[6]); acc[7] = fmaf(w, x3.y, acc[7]);       \
    }

#define LOADP(XX, SS, p)                                                      \
    {                                                                         \
        int _src = __ldg(&g_csr_src[(p)]);                                    \
        XX = __ldg(&((const uint4*)(g_xl + (size_t)_src * HD))[lane]);        \
        SS = __ldg(&g_score[(p) * 4 + h]);                                    \
    }

    {
        uint4 X0, X1; float S0 = 0.f, S1 = 0.f;
        if (beg < end)     LOADP(X0, S0, beg);
        if (beg + 1 < end) LOADP(X1, S1, beg + 1);
        for (int p = beg; p < end; p += 2) {
            PROCESS(X0, S0);
            if (p + 2 < end) LOADP(X0, S0, p + 2);
            if (p + 1 < end) {
                PROCESS(X1, S1);
                if (p + 3 < end) LOADP(X1, S1, p + 3);
            }
        }
    }
#undef LOADP
#undef PROCESS

    float inv = (end > beg) ? 1.f / den : 0.f;
    float v[8];
#pragma unroll
    for (int k = 0; k < 8; k++) v[k] = acc[k] * inv;
#pragma unroll
    for (int k = 0; k < 8; k++) {
        v[k] += __shfl_xor_sync(0xffffffffu, v[k], 8);
        v[k] += __shfl_xor_sync(0xffffffffu, v[k], 16);
    }
    if (lane < 8) {
        float4 b0 = __ldg(&((const float4*)bias)[lane * 2]);
        float4 b1 = __ldg(&((const float4*)bias)[lane * 2 + 1]);
        float o[8];
        o[0] = fmaxf(0.25f * v[0] + b0.x, 0.f);
        o[1] = fmaxf(0.25f * v[1] + b0.y, 0.f);
        o[2] = fmaxf(0.25f * v[2] + b0.z, 0.f);
        o[3] = fmaxf(0.25f * v[3] + b0.w, 0.f);
        o[4] = fmaxf(0.25f * v[4] + b1.x, 0.f);
        o[5] = fmaxf(0.25f * v[5] + b1.y, 0.f);
        o[6] = fmaxf(0.25f * v[6] + b1.z, 0.f);
        o[7] = fmaxf(0.25f * v[7] + b1.w, 0.f);
        if (writeOut) {
            ((float4*)(dout + n * DD))[lane * 2]     = make_float4(o[0], o[1], o[2], o[3]);
            ((float4*)(dout + n * DD))[lane * 2 + 1] = make_float4(o[4], o[5], o[6], o[7]);
        } else {
            __half2 h0 = __floats2half2_rn(o[0], o[1]);
            __half2 h1 = __floats2half2_rn(o[2], o[3]);
            __half2 h2 = __floats2half2_rn(o[4], o[5]);
            __half2 h3 = __floats2half2_rn(o[6], o[7]);
            uint4 u;
            u.x = *(unsigned int*)&h0; u.y = *(unsigned int*)&h1;
            u.z = *(unsigned int*)&h2; u.w = *(unsigned int*)&h3;
            ((uint4*)(g_hh + (size_t)n * DD))[lane] = u;
        }
    }
}

// ---------------- launch ----------------
extern "C" void kernel_launch(void* const* d_in, const int* in_sizes, int n_in,
                              void* d_out, int out_size) {
    const float* x   = (const float*)d_in[0];
    const float* ea  = (const float*)d_in[1];
    const int*   ei  = (const int*)  d_in[2];
    const float* fW  = (const float*)d_in[3];
    const float* fb  = (const float*)d_in[4];
    const float* feW = (const float*)d_in[5];
    const float* feb = (const float*)d_in[6];
    const float* Wl  = (const float*)d_in[7];
    const float* bl  = (const float*)d_in[8];
    const float* Wr  = (const float*)d_in[9];
    const float* br  = (const float*)d_in[10];
    const float* We  = (const float*)d_in[11];
    const float* att = (const float*)d_in[12];
    const float* bias= (const float*)d_in[13];

    // prologue
    k_h0<<<(NN + 15) / 16, 256>>>(x, fW, fb, Wl, Wr, We);
    k_hist<<<(NE + 255) / 256, 256>>>(ei);
    k_scan_a<<<NSB, 256>>>();
    k_scan_bc<<<NSB, 256>>>();
    k_scatter<<<(NE + 255) / 256, 256>>>(ei);

    for (int l = 0; l < 3; l++) {
        k_lin_tc<<<dim3((NN + 127) / 128, 8), 256>>>(bl, br);
        k_score_tc<<<NE / 128, 256>>>(ea, feW, feb, att);
        k_agg<<<(NN + 7) / 8, 256>>>(bias, (float*)d_out, l == 2 ? 1 : 0);
    }
}